// round 3
// baseline (speedup 1.0000x reference)
#include <cuda_runtime.h>
#include <cstdio>

// ---------------------------------------------------------------------------
// Problem constants
// ---------------------------------------------------------------------------
constexpr int kNQ  = 1000;
constexpr int kBS  = 4;
constexpr int kC   = 256;
constexpr int kNH  = 8;
constexpr int kHD  = 32;
constexpr int kNV  = 20000;   // H_BEV * W_BEV = 200*100
constexpr int kFFN = 512;
constexpr int kM   = kBS * kNQ;    // 4000 rows of (b,q)
constexpr int kMV  = kBS * kNV;    // 80000 rows of (b,n)
constexpr float kEPS   = 1e-5f;
constexpr float kScale = 0.17677669529663687f;  // 1/sqrt(HD)

// ---------------------------------------------------------------------------
// Scratch (static device globals -- no cudaMalloc allowed)
// ---------------------------------------------------------------------------
__device__ float g_x0  [kM * kC];           // query transposed to (b,q,c)
__device__ float g_xq  [kM * kC];           // x (+qpos) working buffer
__device__ float g_q   [kM * kC];
__device__ float g_k   [kM * kC];
__device__ float g_v   [kM * kC];
__device__ float g_attn[kM * kC];
__device__ float g_tmp [kM * kFFN];         // proj outputs / FFN hidden
__device__ float g_x1  [kM * kC];
__device__ float g_x2  [kM * kC];
__device__ float g_ms  [kM * kC];           // msdeform out / ffn2 out
__device__ float g_vproj[(size_t)kMV * kC]; // 82 MB projected value
__device__ float g_off [kM * 64];
__device__ float g_aw  [kM * 32];

// ---------------------------------------------------------------------------
// prep: transpose query/query_pos (NQ,BS,C)->(BS,NQ,C); build x0 and x0+pos
// ---------------------------------------------------------------------------
__global__ void prep_kernel(const float* __restrict__ query,
                            const float* __restrict__ qpos)
{
    int i = blockIdx.x * blockDim.x + threadIdx.x;
    if (i >= kM * kC) return;
    int c = i & (kC - 1);
    int r = i >> 8;            // b*kNQ + q
    int b = r / kNQ;
    int q = r - b * kNQ;
    int src = (q * kBS + b) * kC + c;
    float xv = query[src];
    g_x0[i] = xv;
    g_xq[i] = xv + qpos[src];
}

// g_xq = g_x1 + qpos (for msdeform query)
__global__ void addq_kernel(const float* __restrict__ qpos)
{
    int i = blockIdx.x * blockDim.x + threadIdx.x;
    if (i >= kM * kC) return;
    int c = i & (kC - 1);
    int r = i >> 8;
    int b = r / kNQ;
    int q = r - b * kNQ;
    g_xq[i] = g_x1[i] + qpos[(q * kBS + b) * kC + c];
}

// ---------------------------------------------------------------------------
// Generic SGEMM:  C[M,N] = A'[M,K] @ B[N,K]^T + bias[N]   (optional ReLU)
// amode==1: A row m maps to value[(n*BS+b)*K] with m=b*kNV+n  (value transpose)
// ---------------------------------------------------------------------------
__global__ __launch_bounds__(256)
void sgemm_kernel(const float* __restrict__ A, const float* __restrict__ B,
                  const float* __restrict__ bias, float* __restrict__ Co,
                  int M, int N, int K, int amode, int relu)
{
    constexpr int BM = 64, BN = 64, BK = 32, LDSZ = 68;  // +4 pad, 16B aligned
    __shared__ float sA[BK][LDSZ];
    __shared__ float sB[BK][LDSZ];

    int t  = threadIdx.x;
    int tx = t & 15, ty = t >> 4;
    int m0 = blockIdx.y * BM, n0 = blockIdx.x * BN;

    float acc[4][4] = {};

    for (int kt = 0; kt < K; kt += BK) {
        __syncthreads();
#pragma unroll
        for (int ld = 0; ld < 2; ld++) {
            int f   = t + ld * 256;
            int row = f >> 3;
            int kq  = (f & 7) << 2;
            // A tile (store transposed: sA[k][m])
            int m = m0 + row;
            float4 av = make_float4(0.f, 0.f, 0.f, 0.f);
            if (m < M) {
                const float* ap;
                if (amode) {
                    int bb = m / kNV;
                    int n  = m - bb * kNV;
                    ap = A + (size_t)(n * kBS + bb) * K;
                } else {
                    ap = A + (size_t)m * K;
                }
                av = *reinterpret_cast<const float4*>(ap + kt + kq);
            }
            sA[kq + 0][row] = av.x; sA[kq + 1][row] = av.y;
            sA[kq + 2][row] = av.z; sA[kq + 3][row] = av.w;
            // B tile (weights (N,K) row-major -> sB[k][n])
            int n = n0 + row;
            float4 bv = make_float4(0.f, 0.f, 0.f, 0.f);
            if (n < N)
                bv = *reinterpret_cast<const float4*>(B + (size_t)n * K + kt + kq);
            sB[kq + 0][row] = bv.x; sB[kq + 1][row] = bv.y;
            sB[kq + 2][row] = bv.z; sB[kq + 3][row] = bv.w;
        }
        __syncthreads();
#pragma unroll
        for (int kk = 0; kk < BK; kk++) {
            float4 a4 = *reinterpret_cast<const float4*>(&sA[kk][ty << 2]);
            float4 b4 = *reinterpret_cast<const float4*>(&sB[kk][tx << 2]);
            float av[4] = {a4.x, a4.y, a4.z, a4.w};
            float bv[4] = {b4.x, b4.y, b4.z, b4.w};
#pragma unroll
            for (int i = 0; i < 4; i++)
#pragma unroll
                for (int j = 0; j < 4; j++)
                    acc[i][j] = fmaf(av[i], bv[j], acc[i][j]);
        }
    }

    int n = n0 + (tx << 2);
    if (n < N) {
        float4 bz = *reinterpret_cast<const float4*>(bias + n);
#pragma unroll
        for (int i = 0; i < 4; i++) {
            int m = m0 + (ty << 2) + i;
            if (m < M) {
                float4 o;
                o.x = acc[i][0] + bz.x;
                o.y = acc[i][1] + bz.y;
                o.z = acc[i][2] + bz.z;
                o.w = acc[i][3] + bz.w;
                if (relu) {
                    o.x = fmaxf(o.x, 0.f); o.y = fmaxf(o.y, 0.f);
                    o.z = fmaxf(o.z, 0.f); o.w = fmaxf(o.w, 0.f);
                }
                *reinterpret_cast<float4*>(Co + (size_t)m * N + n) = o;
            }
        }
    }
}

// ---------------------------------------------------------------------------
// Flash attention:  per (b,h), 64-query tiles, online softmax over 1000 keys.
// Q/K/V layout: [(b*NQ+q)*C + h*HD + d]
// ---------------------------------------------------------------------------
__global__ __launch_bounds__(256)
void flash_kernel(const float* __restrict__ Q, const float* __restrict__ Kp,
                  const float* __restrict__ V, float* __restrict__ O)
{
    __shared__ float sQ[64][36];
    __shared__ float sK[64][36];
    __shared__ float sV[64][36];
    __shared__ float sP[64][65];

    int b  = blockIdx.y >> 3;
    int h  = blockIdx.y & 7;
    int q0 = blockIdx.x << 6;
    int t  = threadIdx.x;
    int r  = t >> 2;   // row within tile (0..63)
    int c  = t & 3;    // 4 threads per row

    for (int i = t; i < 64 * 32; i += 256) {
        int row = i >> 5, col = i & 31;
        int qq = q0 + row;
        sQ[row][col] = (qq < kNQ)
            ? Q[(size_t)(b * kNQ + qq) * kC + h * kHD + col] : 0.f;
    }
    __syncthreads();

    float4 qv[8];
#pragma unroll
    for (int k = 0; k < 8; k++)
        qv[k] = *reinterpret_cast<const float4*>(&sQ[r][k << 2]);

    float o[8] = {0.f, 0.f, 0.f, 0.f, 0.f, 0.f, 0.f, 0.f};
    float mrow = -1e30f, lrow = 0.f;

    for (int kt = 0; kt < 16; kt++) {
        int k0 = kt << 6;
        __syncthreads();
        for (int i = t; i < 64 * 32; i += 256) {
            int row = i >> 5, col = i & 31;
            int kk = k0 + row;
            bool ok = kk < kNQ;
            size_t gi = (size_t)(b * kNQ + (ok ? kk : 0)) * kC + h * kHD + col;
            sK[row][col] = ok ? Kp[gi] : 0.f;
            sV[row][col] = ok ? V[gi]  : 0.f;
        }
        __syncthreads();

        float s[16];
        float mloc = -1e30f;
#pragma unroll
        for (int jj = 0; jj < 16; jj++) {
            int j = (jj << 2) + c;
            float a = 0.f;
#pragma unroll
            for (int kf = 0; kf < 8; kf++) {
                float4 kv = *reinterpret_cast<const float4*>(&sK[j][kf << 2]);
                a += qv[kf].x * kv.x + qv[kf].y * kv.y
                   + qv[kf].z * kv.z + qv[kf].w * kv.w;
            }
            a *= kScale;
            if (k0 + j >= kNQ) a = -1e30f;
            s[jj] = a;
            mloc = fmaxf(mloc, a);
        }
        mloc = fmaxf(mloc, __shfl_xor_sync(0xffffffffu, mloc, 1));
        mloc = fmaxf(mloc, __shfl_xor_sync(0xffffffffu, mloc, 2));
        float mnew  = fmaxf(mrow, mloc);
        float alpha = __expf(mrow - mnew);
        float lsum  = 0.f;
#pragma unroll
        for (int jj = 0; jj < 16; jj++) {
            float p = __expf(s[jj] - mnew);
            s[jj] = p;
            lsum += p;
        }
        lsum += __shfl_xor_sync(0xffffffffu, lsum, 1);
        lsum += __shfl_xor_sync(0xffffffffu, lsum, 2);
        lrow = lrow * alpha + lsum;
        mrow = mnew;
#pragma unroll
        for (int k = 0; k < 8; k++) o[k] *= alpha;

#pragma unroll
        for (int jj = 0; jj < 16; jj++) sP[r][(jj << 2) + c] = s[jj];
        __syncwarp();
#pragma unroll 8
        for (int j = 0; j < 64; j++) {
            float p = sP[r][j];
            float4 v0 = *reinterpret_cast<const float4*>(&sV[j][(c << 3)]);
            float4 v1 = *reinterpret_cast<const float4*>(&sV[j][(c << 3) + 4]);
            o[0] = fmaf(p, v0.x, o[0]); o[1] = fmaf(p, v0.y, o[1]);
            o[2] = fmaf(p, v0.z, o[2]); o[3] = fmaf(p, v0.w, o[3]);
            o[4] = fmaf(p, v1.x, o[4]); o[5] = fmaf(p, v1.y, o[5]);
            o[6] = fmaf(p, v1.z, o[6]); o[7] = fmaf(p, v1.w, o[7]);
        }
        __syncwarp();
    }

    int qq = q0 + r;
    if (qq < kNQ) {
        float inv = 1.f / lrow;
#pragma unroll
        for (int k = 0; k < 8; k++)
            O[(size_t)(b * kNQ + qq) * kC + h * kHD + (c << 3) + k] = o[k] * inv;
    }
}

// ---------------------------------------------------------------------------
// Residual + LayerNorm:  out = LN(X + Y) * g + b; one block per row (C=256)
// transpose_out: write to (q*BS+b)*C (final output layout)
// ---------------------------------------------------------------------------
__global__ __launch_bounds__(256)
void ln_kernel(const float* __restrict__ X, const float* __restrict__ Y,
               const float* __restrict__ gam, const float* __restrict__ bet,
               float* __restrict__ out, int transpose_out)
{
    int r = blockIdx.x, t = threadIdx.x;
    float v = X[(size_t)r * kC + t] + Y[(size_t)r * kC + t];
    float s1 = v, s2 = v * v;
#pragma unroll
    for (int off = 16; off; off >>= 1) {
        s1 += __shfl_xor_sync(0xffffffffu, s1, off);
        s2 += __shfl_xor_sync(0xffffffffu, s2, off);
    }
    __shared__ float r1[8], r2[8];
    int w = t >> 5, lane = t & 31;
    if (lane == 0) { r1[w] = s1; r2[w] = s2; }
    __syncthreads();
    if (w == 0) {
        float a = (lane < 8) ? r1[lane] : 0.f;
        float bq = (lane < 8) ? r2[lane] : 0.f;
#pragma unroll
        for (int off = 4; off; off >>= 1) {
            a  += __shfl_xor_sync(0xffffffffu, a, off);
            bq += __shfl_xor_sync(0xffffffffu, bq, off);
        }
        if (lane == 0) { r1[0] = a; r2[0] = bq; }
    }
    __syncthreads();
    float mean = r1[0] * (1.f / kC);
    float var  = r2[0] * (1.f / kC) - mean * mean;
    float rstd = rsqrtf(var + kEPS);
    float oo = (v - mean) * rstd * gam[t] + bet[t];
    size_t oi;
    if (transpose_out) {
        int b = r / kNQ, q = r - b * kNQ;
        oi = (size_t)(q * kBS + b) * kC + t;
    } else {
        oi = (size_t)r * kC + t;
    }
    out[oi] = oo;
}

// ---------------------------------------------------------------------------
// Softmax over P=4 attention weights per (b,q,h)  (in place on g_aw)
// ---------------------------------------------------------------------------
__global__ void softmax4_kernel()
{
    int t = blockIdx.x * blockDim.x + threadIdx.x;
    if (t >= kM * kNH) return;
    float* p = g_aw + t * 4;
    float a0 = p[0], a1 = p[1], a2 = p[2], a3 = p[3];
    float mx = fmaxf(fmaxf(a0, a1), fmaxf(a2, a3));
    float e0 = __expf(a0 - mx), e1 = __expf(a1 - mx);
    float e2 = __expf(a2 - mx), e3 = __expf(a3 - mx);
    float inv = 1.f / (e0 + e1 + e2 + e3);
    p[0] = e0 * inv; p[1] = e1 * inv; p[2] = e2 * inv; p[3] = e3 * inv;
}

// ---------------------------------------------------------------------------
// Deformable sampling: one block per (b,q); warp h handles head h, lane = d.
// ---------------------------------------------------------------------------
__global__ __launch_bounds__(256)
void mssample_kernel(const float* __restrict__ refp)
{
    int rq = blockIdx.x;
    int b = rq / kNQ;
    int t = threadIdx.x;
    int h = t >> 5;
    float rx = refp[rq * 2 + 0];   // (BS,NQ,L=1,2) contiguous as rq*2
    float ry = refp[rq * 2 + 1];
    float acc = 0.f;
#pragma unroll
    for (int p = 0; p < 4; p++) {
        float ox = g_off[rq * 64 + h * 8 + p * 2 + 0];
        float oy = g_off[rq * 64 + h * 8 + p * 2 + 1];
        float wa = g_aw [rq * 32 + h * 4 + p];
        float lx = rx + ox / 100.f;     // norm = [W=100, H=200]
        float ly = ry + oy / 200.f;
        float xim = lx * 100.f - 0.5f;  // W_BEV = 100
        float yim = ly * 200.f - 0.5f;  // H_BEV = 200
        float xf = floorf(xim), yf = floorf(yim);
        float fx = xim - xf, fy = yim - yf;
        int x0 = (int)xf, y0 = (int)yf;
        float s = 0.f;
#pragma unroll
        for (int dy = 0; dy < 2; dy++) {
#pragma unroll
            for (int dx = 0; dx < 2; dx++) {
                int xi = x0 + dx, yi = y0 + dy;
                if (xi >= 0 && xi < 100 && yi >= 0 && yi < 200) {
                    float w = (dx ? fx : 1.f - fx) * (dy ? fy : 1.f - fy);
                    s = fmaf(w,
                             g_vproj[(size_t)(b * kNV + yi * 100 + xi) * kC + t],
                             s);
                }
            }
        }
        acc = fmaf(wa, s, acc);
    }
    g_ms[(size_t)rq * kC + t] = acc;
}

// ---------------------------------------------------------------------------
// Launch sequence
// ---------------------------------------------------------------------------
extern "C" void kernel_launch(void* const* d_in, const int* in_sizes, int n_in,
                              void* d_out, int out_size)
{
    const float* query = (const float*)d_in[0];
    const float* value = (const float*)d_in[1];
    const float* qpos  = (const float*)d_in[2];
    const float* refp  = (const float*)d_in[3];
    // d_in[4] spatial_shapes, d_in[5] level_start_index: constants, unused
    const float* in_w  = (const float*)d_in[6];
    const float* in_b  = (const float*)d_in[7];
    const float* mha_ow= (const float*)d_in[8];
    const float* mha_ob= (const float*)d_in[9];
    const float* so_w  = (const float*)d_in[10];
    const float* so_b  = (const float*)d_in[11];
    const float* aw_w  = (const float*)d_in[12];
    const float* aw_b  = (const float*)d_in[13];
    const float* vp_w  = (const float*)d_in[14];
    const float* vp_b  = (const float*)d_in[15];
    const float* op_w  = (const float*)d_in[16];
    const float* op_b  = (const float*)d_in[17];
    const float* f_w1  = (const float*)d_in[18];
    const float* f_b1  = (const float*)d_in[19];
    const float* f_w2  = (const float*)d_in[20];
    const float* f_b2  = (const float*)d_in[21];
    const float* ln1g  = (const float*)d_in[22];
    const float* ln1b  = (const float*)d_in[23];
    const float* ln2g  = (const float*)d_in[24];
    const float* ln2b  = (const float*)d_in[25];
    const float* ln3g  = (const float*)d_in[26];
    const float* ln3b  = (const float*)d_in[27];
    float* out = (float*)d_out;

    float *x0, *xq, *qb, *kb, *vb, *attn, *tmp, *x1, *x2, *vproj, *off, *aw, *ms;
    cudaGetSymbolAddress((void**)&x0,    g_x0);
    cudaGetSymbolAddress((void**)&xq,    g_xq);
    cudaGetSymbolAddress((void**)&qb,    g_q);
    cudaGetSymbolAddress((void**)&kb,    g_k);
    cudaGetSymbolAddress((void**)&vb,    g_v);
    cudaGetSymbolAddress((void**)&attn,  g_attn);
    cudaGetSymbolAddress((void**)&tmp,   g_tmp);
    cudaGetSymbolAddress((void**)&x1,    g_x1);
    cudaGetSymbolAddress((void**)&x2,    g_x2);
    cudaGetSymbolAddress((void**)&vproj, g_vproj);
    cudaGetSymbolAddress((void**)&off,   g_off);
    cudaGetSymbolAddress((void**)&aw,    g_aw);
    cudaGetSymbolAddress((void**)&ms,    g_ms);

    // 1) transpose + add pos
    prep_kernel<<<(kM * kC + 255) / 256, 256>>>(query, qpos);

    // 2) QKV projections (q,k from x+pos; v from x)
    dim3 gC(4, 63);  // N=256/64, ceil(4000/64)
    sgemm_kernel<<<gC, 256>>>(xq, in_w,              in_b,       qb, kM, kC, kC, 0, 0);
    sgemm_kernel<<<gC, 256>>>(xq, in_w + 256 * 256,  in_b + 256, kb, kM, kC, kC, 0, 0);
    sgemm_kernel<<<gC, 256>>>(x0, in_w + 512 * 256,  in_b + 512, vb, kM, kC, kC, 0, 0);

    // 3) fused attention
    flash_kernel<<<dim3(16, kBS * kNH), 256>>>(qb, kb, vb, attn);

    // 4) out-proj + residual + LN1
    sgemm_kernel<<<gC, 256>>>(attn, mha_ow, mha_ob, tmp, kM, kC, kC, 0, 0);
    ln_kernel<<<kM, 256>>>(x0, tmp, ln1g, ln1b, x1, 0);

    // 5) msdeform: q = x1 + pos; offsets + weights
    addq_kernel<<<(kM * kC + 255) / 256, 256>>>(qpos);
    sgemm_kernel<<<dim3(1, 63), 256>>>(xq, so_w, so_b, off, kM, 64, kC, 0, 0);
    sgemm_kernel<<<dim3(1, 63), 256>>>(xq, aw_w, aw_b, aw,  kM, 32, kC, 0, 0);
    softmax4_kernel<<<(kM * kNH + 255) / 256, 256>>>();

    // 6) value projection (A read through (NV,BS,C) transpose) -- biggest GEMM
    sgemm_kernel<<<dim3(4, 1250), 256>>>(value, vp_w, vp_b, vproj, kMV, kC, kC, 1, 0);

    // 7) bilinear sampling + weighted sum
    mssample_kernel<<<kM, 256>>>(refp);

    // 8) msdeform out-proj + residual + LN2
    sgemm_kernel<<<gC, 256>>>(ms, op_w, op_b, tmp, kM, kC, kC, 0, 0);
    ln_kernel<<<kM, 256>>>(x1, tmp, ln2g, ln2b, x2, 0);

    // 9) FFN + residual + LN3 (writes transposed directly into d_out)
    sgemm_kernel<<<dim3(8, 63), 256>>>(x2,  f_w1, f_b1, tmp, kM, kFFN, kC,   0, 1);
    sgemm_kernel<<<gC, 256>>>(tmp, f_w2, f_b2, ms,  kM, kC,   kFFN, 0, 0);
    ln_kernel<<<kM, 256>>>(x2, ms, ln3g, ln3b, out, 1);
}

// round 4
// speedup vs baseline: 1.4108x; 1.4108x over previous
#include <cuda_runtime.h>
#include <cstdint>

// ---------------------------------------------------------------------------
// Problem constants
// ---------------------------------------------------------------------------
constexpr int kNQ  = 1000;
constexpr int kBS  = 4;
constexpr int kC   = 256;
constexpr int kNH  = 8;
constexpr int kHD  = 32;
constexpr int kNV  = 20000;   // H_BEV * W_BEV = 200*100
constexpr int kFFN = 512;
constexpr int kM   = kBS * kNQ;    // 4000 rows of (b,q)
constexpr int kMV  = kBS * kNV;    // 80000 rows of (b,n)
constexpr float kEPS   = 1e-5f;
constexpr float kScale = 0.17677669529663687f;  // 1/sqrt(HD)

// ---------------------------------------------------------------------------
// Scratch (static device globals -- no cudaMalloc allowed)
// ---------------------------------------------------------------------------
__device__ float g_x0  [kM * kC];
__device__ float g_xq  [kM * kC];
__device__ float g_q   [kM * kC];
__device__ float g_k   [kM * kC];
__device__ float g_v   [kM * kC];
__device__ float g_attn[kM * kC];
__device__ float g_tmp [kM * kFFN];
__device__ float g_x1  [kM * kC];
__device__ float g_x2  [kM * kC];
__device__ float g_ms  [kM * kC];
__device__ float g_vproj[(size_t)kMV * kC];
__device__ float g_off [kM * 64];
__device__ float g_aw  [kM * 32];

// ---------------------------------------------------------------------------
// helpers
// ---------------------------------------------------------------------------
__device__ __forceinline__ float tf32r(float x) {
    asm("cvt.rna.tf32.f32 %0, %0;" : "+f"(x));
    return x;
}

__device__ __forceinline__ void mma_tf32(float* c, const uint32_t* a,
                                         const uint32_t* b) {
    asm volatile(
        "mma.sync.aligned.m16n8k8.row.col.f32.tf32.tf32.f32 "
        "{%0,%1,%2,%3}, {%4,%5,%6,%7}, {%8,%9}, {%0,%1,%2,%3};"
        : "+f"(c[0]), "+f"(c[1]), "+f"(c[2]), "+f"(c[3])
        : "r"(a[0]), "r"(a[1]), "r"(a[2]), "r"(a[3]),
          "r"(b[0]), "r"(b[1]));
}

// ---------------------------------------------------------------------------
// prep: transpose query/query_pos (NQ,BS,C)->(BS,NQ,C); build x0 and x0+pos
// ---------------------------------------------------------------------------
__global__ void prep_kernel(const float* __restrict__ query,
                            const float* __restrict__ qpos)
{
    int i = blockIdx.x * blockDim.x + threadIdx.x;
    if (i >= kM * kC) return;
    int c = i & (kC - 1);
    int r = i >> 8;
    int b = r / kNQ;
    int q = r - b * kNQ;
    int src = (q * kBS + b) * kC + c;
    float xv = query[src];
    g_x0[i] = xv;
    g_xq[i] = xv + qpos[src];
}

__global__ void addq_kernel(const float* __restrict__ qpos)
{
    int i = blockIdx.x * blockDim.x + threadIdx.x;
    if (i >= kM * kC) return;
    int c = i & (kC - 1);
    int r = i >> 8;
    int b = r / kNQ;
    int q = r - b * kNQ;
    g_xq[i] = g_x1[i] + qpos[(q * kBS + b) * kC + c];
}

// ---------------------------------------------------------------------------
// TF32 tensor-core GEMM:  C[M,N] = A[M,K] @ W[N,K]^T + bias[N]  (opt. ReLU)
// BM=128 BN=64 BK=32, 256 threads = 8 warps (4m x 2n), warp tile 32x32.
// amode==1: A row m maps to value[((m%NV)*BS + m/NV)*K]  (value transpose)
// ---------------------------------------------------------------------------
__global__ __launch_bounds__(256)
void mma_gemm(const float* __restrict__ A, const float* __restrict__ W,
              const float* __restrict__ bias, float* __restrict__ Co,
              int M, int N, int K, int amode, int relu)
{
    constexpr int BM = 128, BN = 64, BK = 32, LD = BK + 4;
    __shared__ float sA[BM][LD];   // 18 KB
    __shared__ float sB[BN][LD];   // 9 KB

    int t    = threadIdx.x;
    int warp = t >> 5, lane = t & 31;
    int wm0  = (warp >> 1) << 5;   // 0,32,64,96
    int wn0  = (warp & 1) << 5;    // 0,32
    int qr   = lane >> 2;          // 0..7
    int qc   = lane & 3;           // 0..3
    int m0   = blockIdx.y * BM;
    int n0   = blockIdx.x * BN;

    float c[2][4][4] = {};

    for (int kt = 0; kt < K; kt += BK) {
        __syncthreads();
        // A tile: 128x32 floats = 1024 float4, 4 per thread
#pragma unroll
        for (int ld = 0; ld < 4; ld++) {
            int f   = t + (ld << 8);
            int row = f >> 3;
            int col = (f & 7) << 2;
            int m   = m0 + row;
            float4 v = make_float4(0.f, 0.f, 0.f, 0.f);
            if (m < M) {
                const float* ap;
                if (amode) {
                    int bb = m / kNV;
                    int nn = m - bb * kNV;
                    ap = A + (size_t)(nn * kBS + bb) * K;
                } else {
                    ap = A + (size_t)m * K;
                }
                v = *reinterpret_cast<const float4*>(ap + kt + col);
            }
            sA[row][col + 0] = tf32r(v.x);
            sA[row][col + 1] = tf32r(v.y);
            sA[row][col + 2] = tf32r(v.z);
            sA[row][col + 3] = tf32r(v.w);
        }
        // B tile: 64x32 floats = 512 float4, 2 per thread
#pragma unroll
        for (int ld = 0; ld < 2; ld++) {
            int f   = t + (ld << 8);
            int row = f >> 3;
            int col = (f & 7) << 2;
            int n   = n0 + row;
            float4 v = make_float4(0.f, 0.f, 0.f, 0.f);
            if (n < N)
                v = *reinterpret_cast<const float4*>(W + (size_t)n * K + kt + col);
            sB[row][col + 0] = tf32r(v.x);
            sB[row][col + 1] = tf32r(v.y);
            sB[row][col + 2] = tf32r(v.z);
            sB[row][col + 3] = tf32r(v.w);
        }
        __syncthreads();

#pragma unroll
        for (int k8 = 0; k8 < BK; k8 += 8) {
            uint32_t a[2][4];
#pragma unroll
            for (int i = 0; i < 2; i++) {
                int r = wm0 + (i << 4) + qr;
                a[i][0] = __float_as_uint(sA[r    ][k8 + qc]);
                a[i][1] = __float_as_uint(sA[r + 8][k8 + qc]);
                a[i][2] = __float_as_uint(sA[r    ][k8 + qc + 4]);
                a[i][3] = __float_as_uint(sA[r + 8][k8 + qc + 4]);
            }
            uint32_t b[4][2];
#pragma unroll
            for (int j = 0; j < 4; j++) {
                int r = wn0 + (j << 3) + qr;
                b[j][0] = __float_as_uint(sB[r][k8 + qc]);
                b[j][1] = __float_as_uint(sB[r][k8 + qc + 4]);
            }
#pragma unroll
            for (int i = 0; i < 2; i++)
#pragma unroll
                for (int j = 0; j < 4; j++)
                    mma_tf32(c[i][j], a[i], b[j]);
        }
    }

    // epilogue: bias (+ReLU), float2 stores
#pragma unroll
    for (int j = 0; j < 4; j++) {
        int n = n0 + wn0 + (j << 3) + (qc << 1);
        if (n >= N) continue;
        float2 bz = *reinterpret_cast<const float2*>(bias + n);
#pragma unroll
        for (int i = 0; i < 2; i++) {
            int m = m0 + wm0 + (i << 4) + qr;
            if (m < M) {
                float2 o = make_float2(c[i][j][0] + bz.x, c[i][j][1] + bz.y);
                if (relu) { o.x = fmaxf(o.x, 0.f); o.y = fmaxf(o.y, 0.f); }
                *reinterpret_cast<float2*>(Co + (size_t)m * N + n) = o;
            }
            if (m + 8 < M) {
                float2 o = make_float2(c[i][j][2] + bz.x, c[i][j][3] + bz.y);
                if (relu) { o.x = fmaxf(o.x, 0.f); o.y = fmaxf(o.y, 0.f); }
                *reinterpret_cast<float2*>(Co + (size_t)(m + 8) * N + n) = o;
            }
        }
    }
}

// ---------------------------------------------------------------------------
// Flash attention:  per (b,h), 64-query tiles, online softmax over 1000 keys.
// ---------------------------------------------------------------------------
__global__ __launch_bounds__(256)
void flash_kernel(const float* __restrict__ Q, const float* __restrict__ Kp,
                  const float* __restrict__ V, float* __restrict__ O)
{
    __shared__ float sQ[64][36];
    __shared__ float sK[64][36];
    __shared__ float sV[64][36];
    __shared__ float sP[64][65];

    int b  = blockIdx.y >> 3;
    int h  = blockIdx.y & 7;
    int q0 = blockIdx.x << 6;
    int t  = threadIdx.x;
    int r  = t >> 2;
    int c  = t & 3;

    for (int i = t; i < 64 * 32; i += 256) {
        int row = i >> 5, col = i & 31;
        int qq = q0 + row;
        sQ[row][col] = (qq < kNQ)
            ? Q[(size_t)(b * kNQ + qq) * kC + h * kHD + col] : 0.f;
    }
    __syncthreads();

    float4 qv[8];
#pragma unroll
    for (int k = 0; k < 8; k++)
        qv[k] = *reinterpret_cast<const float4*>(&sQ[r][k << 2]);

    float o[8] = {0.f, 0.f, 0.f, 0.f, 0.f, 0.f, 0.f, 0.f};
    float mrow = -1e30f, lrow = 0.f;

    for (int kt = 0; kt < 16; kt++) {
        int k0 = kt << 6;
        __syncthreads();
        for (int i = t; i < 64 * 32; i += 256) {
            int row = i >> 5, col = i & 31;
            int kk = k0 + row;
            bool ok = kk < kNQ;
            size_t gi = (size_t)(b * kNQ + (ok ? kk : 0)) * kC + h * kHD + col;
            sK[row][col] = ok ? Kp[gi] : 0.f;
            sV[row][col] = ok ? V[gi]  : 0.f;
        }
        __syncthreads();

        float s[16];
        float mloc = -1e30f;
#pragma unroll
        for (int jj = 0; jj < 16; jj++) {
            int j = (jj << 2) + c;
            float a = 0.f;
#pragma unroll
            for (int kf = 0; kf < 8; kf++) {
                float4 kv = *reinterpret_cast<const float4*>(&sK[j][kf << 2]);
                a += qv[kf].x * kv.x + qv[kf].y * kv.y
                   + qv[kf].z * kv.z + qv[kf].w * kv.w;
            }
            a *= kScale;
            if (k0 + j >= kNQ) a = -1e30f;
            s[jj] = a;
            mloc = fmaxf(mloc, a);
        }
        mloc = fmaxf(mloc, __shfl_xor_sync(0xffffffffu, mloc, 1));
        mloc = fmaxf(mloc, __shfl_xor_sync(0xffffffffu, mloc, 2));
        float mnew  = fmaxf(mrow, mloc);
        float alpha = __expf(mrow - mnew);
        float lsum  = 0.f;
#pragma unroll
        for (int jj = 0; jj < 16; jj++) {
            float p = __expf(s[jj] - mnew);
            s[jj] = p;
            lsum += p;
        }
        lsum += __shfl_xor_sync(0xffffffffu, lsum, 1);
        lsum += __shfl_xor_sync(0xffffffffu, lsum, 2);
        lrow = lrow * alpha + lsum;
        mrow = mnew;
#pragma unroll
        for (int k = 0; k < 8; k++) o[k] *= alpha;

#pragma unroll
        for (int jj = 0; jj < 16; jj++) sP[r][(jj << 2) + c] = s[jj];
        __syncwarp();
#pragma unroll 8
        for (int j = 0; j < 64; j++) {
            float p = sP[r][j];
            float4 v0 = *reinterpret_cast<const float4*>(&sV[j][(c << 3)]);
            float4 v1 = *reinterpret_cast<const float4*>(&sV[j][(c << 3) + 4]);
            o[0] = fmaf(p, v0.x, o[0]); o[1] = fmaf(p, v0.y, o[1]);
            o[2] = fmaf(p, v0.z, o[2]); o[3] = fmaf(p, v0.w, o[3]);
            o[4] = fmaf(p, v1.x, o[4]); o[5] = fmaf(p, v1.y, o[5]);
            o[6] = fmaf(p, v1.z, o[6]); o[7] = fmaf(p, v1.w, o[7]);
        }
        __syncwarp();
    }

    int qq = q0 + r;
    if (qq < kNQ) {
        float inv = 1.f / lrow;
#pragma unroll
        for (int k = 0; k < 8; k++)
            O[(size_t)(b * kNQ + qq) * kC + h * kHD + (c << 3) + k] = o[k] * inv;
    }
}

// ---------------------------------------------------------------------------
// Residual + LayerNorm
// ---------------------------------------------------------------------------
__global__ __launch_bounds__(256)
void ln_kernel(const float* __restrict__ X, const float* __restrict__ Y,
               const float* __restrict__ gam, const float* __restrict__ bet,
               float* __restrict__ out, int transpose_out)
{
    int r = blockIdx.x, t = threadIdx.x;
    float v = X[(size_t)r * kC + t] + Y[(size_t)r * kC + t];
    float s1 = v, s2 = v * v;
#pragma unroll
    for (int off = 16; off; off >>= 1) {
        s1 += __shfl_xor_sync(0xffffffffu, s1, off);
        s2 += __shfl_xor_sync(0xffffffffu, s2, off);
    }
    __shared__ float r1[8], r2[8];
    int w = t >> 5, lane = t & 31;
    if (lane == 0) { r1[w] = s1; r2[w] = s2; }
    __syncthreads();
    if (w == 0) {
        float a  = (lane < 8) ? r1[lane] : 0.f;
        float bq = (lane < 8) ? r2[lane] : 0.f;
#pragma unroll
        for (int off = 4; off; off >>= 1) {
            a  += __shfl_xor_sync(0xffffffffu, a, off);
            bq += __shfl_xor_sync(0xffffffffu, bq, off);
        }
        if (lane == 0) { r1[0] = a; r2[0] = bq; }
    }
    __syncthreads();
    float mean = r1[0] * (1.f / kC);
    float var  = r2[0] * (1.f / kC) - mean * mean;
    float rstd = rsqrtf(var + kEPS);
    float oo = (v - mean) * rstd * gam[t] + bet[t];
    size_t oi;
    if (transpose_out) {
        int b = r / kNQ, q = r - b * kNQ;
        oi = (size_t)(q * kBS + b) * kC + t;
    } else {
        oi = (size_t)r * kC + t;
    }
    out[oi] = oo;
}

// ---------------------------------------------------------------------------
// Softmax over P=4 weights per (b,q,h)
// ---------------------------------------------------------------------------
__global__ void softmax4_kernel()
{
    int t = blockIdx.x * blockDim.x + threadIdx.x;
    if (t >= kM * kNH) return;
    float* p = g_aw + t * 4;
    float a0 = p[0], a1 = p[1], a2 = p[2], a3 = p[3];
    float mx = fmaxf(fmaxf(a0, a1), fmaxf(a2, a3));
    float e0 = __expf(a0 - mx), e1 = __expf(a1 - mx);
    float e2 = __expf(a2 - mx), e3 = __expf(a3 - mx);
    float inv = 1.f / (e0 + e1 + e2 + e3);
    p[0] = e0 * inv; p[1] = e1 * inv; p[2] = e2 * inv; p[3] = e3 * inv;
}

// ---------------------------------------------------------------------------
// Deformable sampling
// ---------------------------------------------------------------------------
__global__ __launch_bounds__(256)
void mssample_kernel(const float* __restrict__ refp)
{
    int rq = blockIdx.x;
    int b = rq / kNQ;
    int t = threadIdx.x;
    int h = t >> 5;
    float rx = refp[rq * 2 + 0];
    float ry = refp[rq * 2 + 1];
    float acc = 0.f;
#pragma unroll
    for (int p = 0; p < 4; p++) {
        float ox = g_off[rq * 64 + h * 8 + p * 2 + 0];
        float oy = g_off[rq * 64 + h * 8 + p * 2 + 1];
        float wa = g_aw [rq * 32 + h * 4 + p];
        float lx = rx + ox / 100.f;
        float ly = ry + oy / 200.f;
        float xim = lx * 100.f - 0.5f;
        float yim = ly * 200.f - 0.5f;
        float xf = floorf(xim), yf = floorf(yim);
        float fx = xim - xf, fy = yim - yf;
        int x0 = (int)xf, y0 = (int)yf;
        float s = 0.f;
#pragma unroll
        for (int dy = 0; dy < 2; dy++) {
#pragma unroll
            for (int dx = 0; dx < 2; dx++) {
                int xi = x0 + dx, yi = y0 + dy;
                if (xi >= 0 && xi < 100 && yi >= 0 && yi < 200) {
                    float w = (dx ? fx : 1.f - fx) * (dy ? fy : 1.f - fy);
                    s = fmaf(w,
                             g_vproj[(size_t)(b * kNV + yi * 100 + xi) * kC + t],
                             s);
                }
            }
        }
        acc = fmaf(wa, s, acc);
    }
    g_ms[(size_t)rq * kC + t] = acc;
}

// ---------------------------------------------------------------------------
// Launch sequence
// ---------------------------------------------------------------------------
extern "C" void kernel_launch(void* const* d_in, const int* in_sizes, int n_in,
                              void* d_out, int out_size)
{
    const float* query = (const float*)d_in[0];
    const float* value = (const float*)d_in[1];
    const float* qpos  = (const float*)d_in[2];
    const float* refp  = (const float*)d_in[3];
    const float* in_w  = (const float*)d_in[6];
    const float* in_b  = (const float*)d_in[7];
    const float* mha_ow= (const float*)d_in[8];
    const float* mha_ob= (const float*)d_in[9];
    const float* so_w  = (const float*)d_in[10];
    const float* so_b  = (const float*)d_in[11];
    const float* aw_w  = (const float*)d_in[12];
    const float* aw_b  = (const float*)d_in[13];
    const float* vp_w  = (const float*)d_in[14];
    const float* vp_b  = (const float*)d_in[15];
    const float* op_w  = (const float*)d_in[16];
    const float* op_b  = (const float*)d_in[17];
    const float* f_w1  = (const float*)d_in[18];
    const float* f_b1  = (const float*)d_in[19];
    const float* f_w2  = (const float*)d_in[20];
    const float* f_b2  = (const float*)d_in[21];
    const float* ln1g  = (const float*)d_in[22];
    const float* ln1b  = (const float*)d_in[23];
    const float* ln2g  = (const float*)d_in[24];
    const float* ln2b  = (const float*)d_in[25];
    const float* ln3g  = (const float*)d_in[26];
    const float* ln3b  = (const float*)d_in[27];
    float* out = (float*)d_out;

    float *x0, *xq, *qb, *kb, *vb, *attn, *tmp, *x1, *x2, *vproj, *off, *aw, *ms;
    cudaGetSymbolAddress((void**)&x0,    g_x0);
    cudaGetSymbolAddress((void**)&xq,    g_xq);
    cudaGetSymbolAddress((void**)&qb,    g_q);
    cudaGetSymbolAddress((void**)&kb,    g_k);
    cudaGetSymbolAddress((void**)&vb,    g_v);
    cudaGetSymbolAddress((void**)&attn,  g_attn);
    cudaGetSymbolAddress((void**)&tmp,   g_tmp);
    cudaGetSymbolAddress((void**)&x1,    g_x1);
    cudaGetSymbolAddress((void**)&x2,    g_x2);
    cudaGetSymbolAddress((void**)&vproj, g_vproj);
    cudaGetSymbolAddress((void**)&off,   g_off);
    cudaGetSymbolAddress((void**)&aw,    g_aw);
    cudaGetSymbolAddress((void**)&ms,    g_ms);

    // 1) transpose + add pos
    prep_kernel<<<(kM * kC + 255) / 256, 256>>>(query, qpos);

    // 2) QKV projections on tensor pipe
    dim3 gC(4, 32);   // N=256/64, ceil(4000/128)
    mma_gemm<<<gC, 256>>>(xq, in_w,             in_b,       qb, kM, kC, kC, 0, 0);
    mma_gemm<<<gC, 256>>>(xq, in_w + 256 * 256, in_b + 256, kb, kM, kC, kC, 0, 0);
    mma_gemm<<<gC, 256>>>(x0, in_w + 512 * 256, in_b + 512, vb, kM, kC, kC, 0, 0);

    // 3) fused attention
    flash_kernel<<<dim3(16, kBS * kNH), 256>>>(qb, kb, vb, attn);

    // 4) out-proj + residual + LN1
    mma_gemm<<<gC, 256>>>(attn, mha_ow, mha_ob, tmp, kM, kC, kC, 0, 0);
    ln_kernel<<<kM, 256>>>(x0, tmp, ln1g, ln1b, x1, 0);

    // 5) msdeform: q = x1 + pos; offsets + weights
    addq_kernel<<<(kM * kC + 255) / 256, 256>>>(qpos);
    mma_gemm<<<dim3(1, 32), 256>>>(xq, so_w, so_b, off, kM, 64, kC, 0, 0);
    mma_gemm<<<dim3(1, 32), 256>>>(xq, aw_w, aw_b, aw,  kM, 32, kC, 0, 0);
    softmax4_kernel<<<(kM * kNH + 255) / 256, 256>>>();

    // 6) value projection (transpose-read), biggest GEMM
    mma_gemm<<<dim3(4, 625), 256>>>(value, vp_w, vp_b, vproj, kMV, kC, kC, 1, 0);

    // 7) bilinear sampling + weighted sum
    mssample_kernel<<<kM, 256>>>(refp);

    // 8) msdeform out-proj + residual + LN2
    mma_gemm<<<gC, 256>>>(ms, op_w, op_b, tmp, kM, kC, kC, 0, 0);
    ln_kernel<<<kM, 256>>>(x1, tmp, ln2g, ln2b, x2, 0);

    // 9) FFN + residual + LN3 (LN3 writes transposed into d_out)
    mma_gemm<<<dim3(8, 32), 256>>>(x2,  f_w1, f_b1, tmp, kM, kFFN, kC,   0, 1);
    mma_gemm<<<gC, 256>>>(tmp, f_w2, f_b2, ms,  kM, kC,   kFFN, 0, 0);
    ln_kernel<<<kM, 256>>>(x2, ms, ln3g, ln3b, out, 1);
}